// round 4
// baseline (speedup 1.0000x reference)
#include <cuda_runtime.h>
#include <cuda_bf16.h>

// PointPillarsScatter: out[b, c, y, x] = feat[n, c] where coords[n] = (b, _, y, x), else 0.
// Strategy: inverse-index gather. memset g_map to -1, scatter pillar index n into
// g_map[b,y,x], then write the 219MB output exactly once with coalesced float4
// streaming stores. Channel loop split 4 ways (16 ch/thread) for occupancy + store MLP.

#define NYd 496
#define NXd 432
#define Cd  64
#define Bd  4
#define HWd (NYd * NXd)          // 214272
#define MAPN (Bd * HWd)          // 857088 ints, 3.4 MB scratch

__device__ int g_map[MAPN];

// ---- Kernel 1: scatter pillar index into map (map pre-set to -1 via memset) ----
__global__ void scatter_map_kernel(const int* __restrict__ coords, int n_total) {
    int n = blockIdx.x * blockDim.x + threadIdx.x;
    if (n >= n_total) return;
    int4 cc = ((const int4*)coords)[n];   // (b, z, y, x)
    g_map[(cc.x * NYd + cc.z) * NXd + cc.w] = n;
}

// ---- Kernel 2: gather-write output, coalesced float4 streaming stores ----
// One thread per (quarter, b, y, x/4); each thread covers 16 channels.
// 'quarter' is the outermost (slow) dimension so warp lanes stay consecutive
// in x -> 512B contiguous stores. 32-bit feature offsets keep regs low.
__global__ void __launch_bounds__(256) write_out_kernel(
        const float* __restrict__ feat, float* __restrict__ out) {
    const int XV = NXd / 4;  // 108
    const int CQ = Cd / 4;   // 16 channels per thread
    int tid = blockIdx.x * blockDim.x + threadIdx.x;
    if (tid >= 4 * Bd * NYd * XV) return;

    int t  = tid;
    int x4 = t % XV;  t /= XV;
    int y  = t % NYd; t /= NYd;
    int b  = t % Bd;
    int q  = t / Bd;            // 0..3
    int c0 = q * CQ;            // 0,16,32,48

    int4 m = *(const int4*)&g_map[(b * NYd + y) * NXd + x4 * 4];

    bool ok0 = m.x >= 0, ok1 = m.y >= 0, ok2 = m.z >= 0, ok3 = m.w >= 0;
    // 32-bit element offsets into feat (max 48000*64+63 < 2^31)
    int o0 = m.x * Cd + c0;
    int o1 = m.y * Cd + c0;
    int o2 = m.z * Cd + c0;
    int o3 = m.w * Cd + c0;

    // out offset for channel c: ((b*C + c0 + c)*NY + y)*NX + x
    float* outp = out + ((b * Cd + c0) * NYd + y) * NXd + x4 * 4;

    #pragma unroll
    for (int c = 0; c < CQ; c++) {
        float4 v;
        v.x = ok0 ? __ldg(feat + o0 + c) : 0.0f;
        v.y = ok1 ? __ldg(feat + o1 + c) : 0.0f;
        v.z = ok2 ? __ldg(feat + o2 + c) : 0.0f;
        v.w = ok3 ? __ldg(feat + o3 + c) : 0.0f;
        __stcs((float4*)(outp + c * HWd), v);
    }
}

extern "C" void kernel_launch(void* const* d_in, const int* in_sizes, int n_in,
                              void* d_out, int out_size) {
    const float* feat   = (const float*)d_in[0];
    const int*   coords = (const int*)d_in[1];
    int n_total = in_sizes[1] / 4;

    // 1) map := -1 (0xFF bytes) — async memset node, graph-capturable, no alloc
    void* map_ptr = nullptr;
    cudaGetSymbolAddress(&map_ptr, g_map);
    cudaMemsetAsync(map_ptr, 0xFF, (size_t)MAPN * sizeof(int), 0);

    // 2) map[idx] = n
    scatter_map_kernel<<<(n_total + 255) / 256, 256>>>(coords, n_total);

    // 3) gather-write full output (4 threads per cell-quad: 16 channels each)
    {
        int nthreads = 4 * Bd * NYd * (NXd / 4);   // 857088
        write_out_kernel<<<(nthreads + 255) / 256, 256>>>(feat, (float*)d_out);
    }
}